// round 3
// baseline (speedup 1.0000x reference)
#include <cuda_runtime.h>
#include <cstddef>

// Two-layer LSTM recurrence, persistent kernel, gate-paired f32x2 GEMV.
// Pairing: accumulators (i,f) and (g,o) per batch elem; W stored gate-
// interleaved so pairs load directly; h stored lane-duplicated in SMEM so
// pairs load directly. Zero runtime packing instructions in the inner loop.

#define CELL     100
#define NB       32       // batch per block
#define BT       4        // batch per layer-1 thread
#define THREADS  928
#define L2BASE   800      // first layer-2 thread
#define WSTRIDE  408      // floats per unit row of Wint (bank-spread padding)

#define FMA2(acc, a, b) asm("fma.rn.f32x2 %0,%1,%2,%0;" : "+l"(acc) : "l"(a), "l"(b))
#define UNPK2(lo, hi, s) asm("mov.b64 {%0,%1},%2;" : "=f"(lo), "=f"(hi) : "l"(s))

__device__ __forceinline__ float sigm(float x) {
    return 1.0f / (1.0f + __expf(-x));
}
__device__ __forceinline__ float tanh_f(float x) {
    float e = __expf(2.0f * x);
    return 1.0f - 2.0f / (e + 1.0f);
}

__global__ void __launch_bounds__(THREADS, 1)
tsrnn_kernel(const float* __restrict__ input,
             const float* __restrict__ W_ih1, const float* __restrict__ W_hh1,
             const float* __restrict__ b_ih1, const float* __restrict__ b_hh1,
             const float* __restrict__ W_ih2, const float* __restrict__ W_hh2,
             const float* __restrict__ b_ih2, const float* __restrict__ b_hh2,
             float* __restrict__ out, int T, int FUT, int Btot)
{
    extern __shared__ float sm[];
    float* Wint = sm;                      // [100][WSTRIDE] : u*408 + j*4 + gate
    float* hdup = Wint + CELL * WSTRIDE;   // [100][64]  h1 lane-duplicated
    float* c1sh = hdup + CELL * 64;        // [100][32]  c1
    float* w2sh = c1sh + CELL * NB;        // [4][100]
    float* g2sh = w2sh + 4 * CELL;         // [4][32]
    float* c2sh = g2sh + 4 * NB;           // [32]

    const int tid    = threadIdx.x;
    const int bglob0 = blockIdx.x * NB;

    const bool l1 = (tid < L2BASE);
    const int  u  = tid >> 3;              // layer-1 unit (0..99)
    const int  t8 = tid & 7;               // batch subgroup
    const int  b0 = t8 * BT;               // first batch elem

    // ---- stage weights: gate-interleaved, padded row ----
    for (int idx = tid; idx < 4 * CELL * CELL; idx += THREADS) {
        int k = idx & 3, r = idx >> 2;
        int uu = r / CELL, j = r - uu * CELL;
        Wint[uu * WSTRIDE + j * 4 + k] = W_hh1[(k * CELL + uu) * CELL + j];
    }
    for (int idx = tid; idx < 4 * CELL; idx += THREADS) w2sh[idx] = W_ih2[idx];
    for (int idx = tid; idx < CELL * 64; idx += THREADS) hdup[idx] = 0.0f;
    for (int idx = tid; idx < CELL * NB; idx += THREADS) c1sh[idx] = 0.0f;
    if (tid < NB) c2sh[tid] = 0.0f;

    // layer-1 per-thread constants
    float wih[4], bsum[4];
    if (l1) {
        #pragma unroll
        for (int k = 0; k < 4; k++) {
            int g = k * CELL + u;
            wih[k]  = W_ih1[g];
            bsum[k] = b_ih1[g] + b_hh1[g];
        }
    }
    // layer-2 per-thread constants + state
    const int r2 = tid - L2BASE;           // 0..127 for l2 threads
    float whh2[4], b2c[4];
    float h2 = 0.0f, c2 = 0.0f;
    if (!l1 && r2 < NB) {
        #pragma unroll
        for (int k = 0; k < 4; k++) {
            whh2[k] = W_hh2[k];
            b2c[k]  = b_ih2[k] + b_hh2[k];
        }
    }

    float c1r[BT];
    #pragma unroll
    for (int bb = 0; bb < BT; bb++) c1r[bb] = 0.0f;

    const float* wp  = Wint + u * WSTRIDE;
    const float* h1p = hdup + 4 * t8;        // dup pairs for b0, b0+1
    const float* h2p = hdup + 32 + 4 * t8;   // dup pairs for b0+2, b0+3

    // ================= layer-1 step =================
    auto layer1_step = [&](const float4 xq) {
        unsigned long long Aif0 = 0ull, Aif1 = 0ull, Aif2 = 0ull, Aif3 = 0ull,
                           Ago0 = 0ull, Ago1 = 0ull, Ago2 = 0ull, Ago3 = 0ull;
        #pragma unroll 4
        for (int j = 0; j < CELL; j++) {
            ulonglong2 wv = *(const ulonglong2*)(wp + j * 4);   // (wi,wf),(wg,wo)
            ulonglong2 hA = *(const ulonglong2*)(h1p + j * 64); // {h0,h0},{h1,h1}
            ulonglong2 hB = *(const ulonglong2*)(h2p + j * 64); // {h2,h2},{h3,h3}
            FMA2(Aif0, wv.x, hA.x); FMA2(Ago0, wv.y, hA.x);
            FMA2(Aif1, wv.x, hA.y); FMA2(Ago1, wv.y, hA.y);
            FMA2(Aif2, wv.x, hB.x); FMA2(Ago2, wv.y, hB.x);
            FMA2(Aif3, wv.x, hB.y); FMA2(Ago3, wv.y, hB.y);
        }
        float gi[BT], gf[BT], gg[BT], go[BT];
        UNPK2(gi[0], gf[0], Aif0); UNPK2(gg[0], go[0], Ago0);
        UNPK2(gi[1], gf[1], Aif1); UNPK2(gg[1], go[1], Ago1);
        UNPK2(gi[2], gf[2], Aif2); UNPK2(gg[2], go[2], Ago2);
        UNPK2(gi[3], gf[3], Aif3); UNPK2(gg[3], go[3], Ago3);

        const float xv[BT] = {xq.x, xq.y, xq.z, xq.w};
        float hn[BT], cn[BT];
        #pragma unroll
        for (int bb = 0; bb < BT; bb++) {
            float pi = fmaf(xv[bb], wih[0], gi[bb] + bsum[0]);
            float pf = fmaf(xv[bb], wih[1], gf[bb] + bsum[1]);
            float pg = fmaf(xv[bb], wih[2], gg[bb] + bsum[2]);
            float po = fmaf(xv[bb], wih[3], go[bb] + bsum[3]);
            float c  = sigm(pf) * c1r[bb] + sigm(pi) * tanh_f(pg);
            c1r[bb] = c;
            cn[bb]  = c;
            hn[bb]  = sigm(po) * tanh_f(c);
        }
        // stash for write phase (after the sync)
        return make_float4(hn[0], hn[1], hn[2], hn[3]);
    };

    auto l1_write = [&](float4 hn) {
        *(float4*)(hdup + u * 64 + 4 * t8)      = make_float4(hn.x, hn.x, hn.y, hn.y);
        *(float4*)(hdup + u * 64 + 32 + 4 * t8) = make_float4(hn.z, hn.z, hn.w, hn.w);
        *(float4*)(c1sh + u * NB + b0)          = make_float4(c1r[0], c1r[1], c1r[2], c1r[3]);
    };

    // ================= layer-2 step =================
    auto layer2_step = [&](int tt, bool wr_out) {
        int k = r2 >> 5, b = r2 & 31;
        const float* wr = w2sh + k * CELL;
        const float* cp = c1sh + b;
        float d0 = 0.f, d1 = 0.f, d2 = 0.f, d3 = 0.f;
        #pragma unroll 5
        for (int uu = 0; uu < CELL; uu += 4) {
            d0 = fmaf(cp[(uu + 0) * NB], wr[uu + 0], d0);
            d1 = fmaf(cp[(uu + 1) * NB], wr[uu + 1], d1);
            d2 = fmaf(cp[(uu + 2) * NB], wr[uu + 2], d2);
            d3 = fmaf(cp[(uu + 3) * NB], wr[uu + 3], d3);
        }
        g2sh[k * NB + b] = (d0 + d1) + (d2 + d3);
        asm volatile("bar.sync 1, 128;" ::: "memory");
        if (r2 < NB) {
            float pi = fmaf(h2, whh2[0], g2sh[0 * NB + r2] + b2c[0]);
            float pf = fmaf(h2, whh2[1], g2sh[1 * NB + r2] + b2c[1]);
            float pg = fmaf(h2, whh2[2], g2sh[2 * NB + r2] + b2c[2]);
            float po = fmaf(h2, whh2[3], g2sh[3 * NB + r2] + b2c[3]);
            float c  = sigm(pf) * c2 + sigm(pi) * tanh_f(pg);
            c2 = c;
            h2 = sigm(po) * tanh_f(c);
            c2sh[r2] = c;
            if (wr_out) out[(size_t)(bglob0 + r2) * FUT + (tt - T)] = c;
        }
    };

    __syncthreads();

    // ===== observed phase: l2 pipelined one step behind, 2 syncs/step =====
    for (int t = 0; t < T; ++t) {
        float4 hn;
        if (l1) {
            float4 xq = *(const float4*)(input + (size_t)t * Btot + bglob0 + b0);
            hn = layer1_step(xq);          // reads hdup (step t-1), c1sh untouched
        } else if (t > 0) {
            layer2_step(t - 1, false);     // reads c1sh (step t-1)
        }
        __syncthreads();                   // all reads of hdup/c1sh done
        if (l1) l1_write(hn);
        __syncthreads();                   // new h/c1 visible
    }
    // drain layer-2 for step T-1
    if (!l1) layer2_step(T - 1, false);
    __syncthreads();

    // ===== future phase: strictly serial, 3 syncs/step =====
    const int TOT = T + FUT;
    for (int t = T; t < TOT; ++t) {
        float4 hn;
        if (l1) {
            float4 xq = *(const float4*)(c2sh + b0);
            hn = layer1_step(xq);
        }
        __syncthreads();
        if (l1) l1_write(hn);
        __syncthreads();
        if (!l1) layer2_step(t, true);
        __syncthreads();
    }
}

extern "C" void kernel_launch(void* const* d_in, const int* in_sizes, int n_in,
                              void* d_out, int out_size)
{
    const float* input = (const float*)d_in[0];
    const float* W_ih1 = (const float*)d_in[1];
    const float* W_hh1 = (const float*)d_in[2];
    const float* b_ih1 = (const float*)d_in[3];
    const float* b_hh1 = (const float*)d_in[4];
    const float* W_ih2 = (const float*)d_in[5];
    const float* W_hh2 = (const float*)d_in[6];
    const float* b_ih2 = (const float*)d_in[7];
    const float* b_hh2 = (const float*)d_in[8];
    float* out = (float*)d_out;

    const int Btot = 4096;
    const int T    = in_sizes[0] / Btot;   // 512
    const int FUT  = out_size   / Btot;    // 64

    const int smem = (CELL * WSTRIDE     // Wint      40800
                      + CELL * 64        // hdup       6400
                      + CELL * NB        // c1sh       3200
                      + 4 * CELL         // w2sh        400
                      + 4 * NB           // g2sh        128
                      + NB)              // c2sh         32
                     * (int)sizeof(float);  // = 203,840 B

    cudaFuncSetAttribute(tsrnn_kernel,
                         cudaFuncAttributeMaxDynamicSharedMemorySize, smem);

    tsrnn_kernel<<<Btot / NB, THREADS, smem>>>(
        input, W_ih1, W_hh1, b_ih1, b_hh1,
        W_ih2, W_hh2, b_ih2, b_hh2,
        out, T, FUT, Btot);
}